// round 12
// baseline (speedup 1.0000x reference)
#include <cuda_runtime.h>
#include <cuda_bf16.h>
#include <cstdint>

// Problem constants
#define B_   4
#define C_   256
#define H_   64
#define W_   64
#define HID  64
#define KCH  100      // s*s*k*k
#define SS   4        // s*s
#define KK   25       // k*k
#define HW   4096     // H*W
#define BN_EPS 1e-5f

// Scratch (static device allocations — allowed)
__device__ float g_h[B_ * HID * HW];        // 4 MB
__device__ float g_kern[B_ * KCH * HW];     // 6.55 MB
__device__ float g_sc[HID];
__device__ float g_sh[HID];

// ---------------------------------------------------------------------------
// cp.async helpers (4-byte, zero-fill via src-size=0 for OOB)
// ---------------------------------------------------------------------------
__device__ __forceinline__ void cp_async_f32(uint32_t smem_addr,
                                             const float* gptr, bool valid)
{
    const int sz = valid ? 4 : 0;
    asm volatile("cp.async.ca.shared.global [%0], [%1], 4, %2;\n"
                 :: "r"(smem_addr), "l"(gptr), "r"(sz));
}
#define CP_COMMIT() asm volatile("cp.async.commit_group;\n" ::: "memory")
#define CP_WAIT0()  asm volatile("cp.async.wait_group 0;\n" ::: "memory")

// ---------------------------------------------------------------------------
// Kernel 1: h[b,o,p] = sum_c w1[o,c] * x[b,c,p]
// grid (32, B, 4) = 512 blocks x 128 threads (fine-grained wave balance)
// ---------------------------------------------------------------------------
__global__ __launch_bounds__(128) void k1_gemm1(
    const float* __restrict__ x, const float* __restrict__ w1)
{
    __shared__ float4 w1s[16 * 64];   // 16 outputs x 256 c (as float4)
    const int b  = blockIdx.y;
    const int og = blockIdx.z;
    const int tid = threadIdx.x;

    const float4* w1g = (const float4*)(w1 + og * 16 * C_);
    for (int i = tid; i < 16 * 64; i += 128) w1s[i] = w1g[i];
    __syncthreads();

    const int p = blockIdx.x * 128 + tid;
    const float* xb = x + (size_t)b * C_ * HW + p;

    float acc[16];
#pragma unroll
    for (int o = 0; o < 16; o++) acc[o] = 0.f;

    for (int c = 0; c < C_; c += 4) {
        float xv0 = xb[(c + 0) * HW];
        float xv1 = xb[(c + 1) * HW];
        float xv2 = xb[(c + 2) * HW];
        float xv3 = xb[(c + 3) * HW];
#pragma unroll
        for (int o = 0; o < 16; o++) {
            float4 w = w1s[o * 64 + (c >> 2)];
            acc[o] += w.x * xv0 + w.y * xv1 + w.z * xv2 + w.w * xv3;
        }
    }

    float* hb = g_h + ((size_t)b * HID + og * 16) * HW + p;
#pragma unroll
    for (int o = 0; o < 16; o++) hb[o * HW] = acc[o];
}

// ---------------------------------------------------------------------------
// Kernel 2: per-channel batch-norm statistics -> scale/shift (512 threads)
// ---------------------------------------------------------------------------
__global__ __launch_bounds__(512) void k2_stats(
    const float* __restrict__ gamma, const float* __restrict__ beta)
{
    const int o = blockIdx.x;
    const int tid = threadIdx.x;
    float s = 0.f, s2 = 0.f;
    for (int b = 0; b < B_; b++) {
        const float* hp = g_h + ((size_t)b * HID + o) * HW;
        for (int i = tid; i < HW; i += 512) {
            float v = hp[i];
            s += v; s2 += v * v;
        }
    }
#pragma unroll
    for (int off = 16; off; off >>= 1) {
        s  += __shfl_down_sync(0xffffffffu, s,  off);
        s2 += __shfl_down_sync(0xffffffffu, s2, off);
    }
    __shared__ float rs[16], rs2[16];
    if ((tid & 31) == 0) { rs[tid >> 5] = s; rs2[tid >> 5] = s2; }
    __syncthreads();
    if (tid == 0) {
        float ts = 0.f, ts2 = 0.f;
#pragma unroll
        for (int w = 0; w < 16; w++) { ts += rs[w]; ts2 += rs2[w]; }
        const float invN = 1.f / (float)(B_ * HW);
        float mean  = ts * invN;
        float var   = ts2 * invN - mean * mean;
        float scale = gamma[o] * rsqrtf(var + BN_EPS);
        g_sc[o] = scale;
        g_sh[o] = beta[o] - mean * scale;
    }
}

// ---------------------------------------------------------------------------
// Kernel 3: BN apply + ReLU + GEMM2 + softmax over k*k, per s-group.
// grid (32, B, SS) = 512 blocks x 128 threads.
// ---------------------------------------------------------------------------
__global__ __launch_bounds__(128) void k3_kern(
    const float* __restrict__ w2, const float* __restrict__ b2)
{
    __shared__ float4 w2s[KK * 16];   // 25 outputs x 64 c (as float4)
    __shared__ float b2s[KK], scs[HID], shs[HID];
    const int b = blockIdx.y, g = blockIdx.z, tid = threadIdx.x;

    const float4* w2g = (const float4*)(w2 + g * KK * HID);
    for (int i = tid; i < KK * 16; i += 128) w2s[i] = w2g[i];
    if (tid < KK)  b2s[tid] = b2[g * KK + tid];
    if (tid < HID) { scs[tid] = g_sc[tid]; shs[tid] = g_sh[tid]; }
    __syncthreads();

    const int p = blockIdx.x * 128 + tid;
    const float* hb = g_h + (size_t)b * HID * HW + p;

    float a[HID];
#pragma unroll
    for (int c = 0; c < HID; c++)
        a[c] = fmaxf(fmaf(hb[c * HW], scs[c], shs[c]), 0.f);

    float v[KK];
    float vmax = -1e30f;
#pragma unroll
    for (int q = 0; q < KK; q++) {
        float acc = b2s[q];
#pragma unroll
        for (int c4 = 0; c4 < 16; c4++) {
            float4 w = w2s[q * 16 + c4];
            acc += w.x * a[4 * c4] + w.y * a[4 * c4 + 1]
                 + w.z * a[4 * c4 + 2] + w.w * a[4 * c4 + 3];
        }
        v[q] = acc;
        vmax = fmaxf(vmax, acc);
    }
    float ssum = 0.f;
#pragma unroll
    for (int q = 0; q < KK; q++) { v[q] = __expf(v[q] - vmax); ssum += v[q]; }
    float inv = 1.f / ssum;

    float* kb = g_kern + ((size_t)b * KCH + g * KK) * HW + p;
#pragma unroll
    for (int q = 0; q < KK; q++) kb[q * HW] = v[q] * inv;
}

// ---------------------------------------------------------------------------
// Kernel 4 (v4): reassembly + pixel shuffle, cp.async double-buffered halo.
// Thread = (pixel, si-half): kr[50], 4 channels/step via float4 smem loads.
// Block = 128 thr, tile 16x4, halo 20x8. CSPLIT=4 -> 64 ch/block,
// grid = 1024 blocks. cp.async GMEM->SMEM prefetch frees the 20 vregs the
// old register-prefetch burned -> 5 resident blocks (was 4).
// ---------------------------------------------------------------------------
#define CSPLIT 4
#define CPB    (C_ / CSPLIT)     // 64 channels per block
#define TW4 16
#define TH4 4
#define HWID 20                  // halo width
#define HHGT 8                   // halo height
#define NQ  4                    // channel-quads per phase (16 channels)
#define HSLOTS (NQ * HHGT * HWID)  // 640 float4 slots
#define NPHASE (CPB / (NQ * 4))    // 4
#define LPT (HSLOTS / 128)         // 5 halo slots per thread

__global__ __launch_bounds__(128, 5) void k4_reassemble(
    const float* __restrict__ x, float* __restrict__ out)
{
    __shared__ float4 xs4[2][HSLOTS];   // 2 x 10 KB

    const int bz    = blockIdx.z;
    const int b     = bz >> 2;            // CSPLIT = 4
    const int cbase = (bz & 3) * CPB;
    const int tid   = threadIdx.x;
    const int lane  = tid & 31;
    const int wrow  = tid >> 5;           // tile row 0..3
    const int pxl   = lane & 15;
    const int si    = lane >> 4;          // 0 or 1
    const int px    = blockIdx.x * TW4 + pxl;
    const int py    = blockIdx.y * TH4 + wrow;
    const int p     = py * W_ + px;

    const float* xb = x + (size_t)b * C_ * HW;
    const int h0 = blockIdx.y * TH4 - 2;
    const int w0 = blockIdx.x * TW4 - 2;

    // Per-thread halo-load slots (fixed across phases)
    int  goff[LPT];
    bool gval[LPT];
#pragma unroll
    for (int j = 0; j < LPT; j++) {
        const int i   = tid + j * 128;
        const int q   = i / (HHGT * HWID);
        const int rem = i - q * (HHGT * HWID);
        const int r   = rem / HWID;
        const int cc  = rem - r * HWID;
        const int gh = h0 + r, gw = w0 + cc;
        gval[j] = ((unsigned)gh < (unsigned)H_) && ((unsigned)gw < (unsigned)W_);
        goff[j] = (q * 4) * HW + (gval[j] ? (gh * W_ + gw) : 0);
    }

    // Issue phase-0 halo via cp.async (overlaps with the kr LDGs below)
    {
        const float* base = xb + (size_t)cbase * HW;
#pragma unroll
        for (int j = 0; j < LPT; j++) {
            const uint32_t sdst =
                (uint32_t)__cvta_generic_to_shared(&xs4[0][tid + j * 128]);
            const float* gp = base + goff[j];
#pragma unroll
            for (int k = 0; k < 4; k++)
                cp_async_f32(sdst + 4 * k, gp + k * HW, gval[j]);
        }
        CP_COMMIT();
    }

    // 50 softmax weights: groups si*2+0 and si*2+1
    float kr[50];
    {
        const float* kb = g_kern + ((size_t)b * KCH + si * 50) * HW + p;
#pragma unroll
        for (int j = 0; j < 50; j++) kr[j] = kb[j * HW];
    }

    float* ob = out + (size_t)b * C_ * (4 * HW)
              + (size_t)(2 * py + si) * (2 * W_) + 2 * px;

    CP_WAIT0();
    __syncthreads();

#pragma unroll 1
    for (int phase = 0; phase < NPHASE; phase++) {
        const int cph = cbase + phase * (NQ * 4);
        const int buf = phase & 1;
        const bool has_next = (phase + 1 < NPHASE);

        // Issue next phase's halo into the other buffer (async, no regs held)
        if (has_next) {
            const float* base = xb + (size_t)(cph + NQ * 4) * HW;
#pragma unroll
            for (int j = 0; j < LPT; j++) {
                const uint32_t sdst =
                    (uint32_t)__cvta_generic_to_shared(&xs4[buf ^ 1][tid + j * 128]);
                const float* gp = base + goff[j];
#pragma unroll
                for (int k = 0; k < 4; k++)
                    cp_async_f32(sdst + 4 * k, gp + k * HW, gval[j]);
            }
            CP_COMMIT();
        }

        // Compute from current buffer
#pragma unroll 1
        for (int q = 0; q < NQ; q++) {
            const float4* t = xs4[buf] + (q * HHGT + wrow) * HWID + pxl;
            float ax0 = 0.f, ay0 = 0.f, az0 = 0.f, aw0 = 0.f;   // sj = 0
            float ax1 = 0.f, ay1 = 0.f, az1 = 0.f, aw1 = 0.f;   // sj = 1
#pragma unroll
            for (int di = 0; di < 5; di++) {
#pragma unroll
                for (int dj = 0; dj < 5; dj++) {
                    const float4 xv = t[di * HWID + dj];
                    const float wA = kr[di * 5 + dj];
                    const float wB = kr[25 + di * 5 + dj];
                    ax0 = fmaf(wA, xv.x, ax0);  ax1 = fmaf(wB, xv.x, ax1);
                    ay0 = fmaf(wA, xv.y, ay0);  ay1 = fmaf(wB, xv.y, ay1);
                    az0 = fmaf(wA, xv.z, az0);  az1 = fmaf(wB, xv.z, az1);
                    aw0 = fmaf(wA, xv.w, aw0);  aw1 = fmaf(wB, xv.w, aw1);
                }
            }
            float* oc = ob + (size_t)(cph + q * 4) * (4 * HW);
            *(float2*)oc = make_float2(ax0, ax1);  oc += 4 * HW;
            *(float2*)oc = make_float2(ay0, ay1);  oc += 4 * HW;
            *(float2*)oc = make_float2(az0, az1);  oc += 4 * HW;
            *(float2*)oc = make_float2(aw0, aw1);
        }

        if (has_next) {
            CP_WAIT0();
            __syncthreads();
        }
    }
}

// ---------------------------------------------------------------------------
extern "C" void kernel_launch(void* const* d_in, const int* in_sizes, int n_in,
                              void* d_out, int out_size)
{
    const float* x     = (const float*)d_in[0];   // [4,256,64,64]
    const float* w1    = (const float*)d_in[1];   // [64,256]
    const float* gamma = (const float*)d_in[2];   // [64]
    const float* beta  = (const float*)d_in[3];   // [64]
    const float* w2    = (const float*)d_in[4];   // [100,64]
    const float* b2    = (const float*)d_in[5];   // [100]
    float* out = (float*)d_out;                   // [4,256,128,128]

    k1_gemm1<<<dim3(32, B_, 4), 128>>>(x, w1);
    k2_stats<<<dim3(HID), 512>>>(gamma, beta);
    k3_kern<<<dim3(32, B_, SS), 128>>>(w2, b2);
    k4_reassemble<<<dim3(W_ / TW4, H_ / TH4, B_ * CSPLIT), 128>>>(x, out);
}

// round 13
// speedup vs baseline: 1.0422x; 1.0422x over previous
#include <cuda_runtime.h>
#include <cuda_bf16.h>
#include <cstdint>

// Problem constants
#define B_   4
#define C_   256
#define H_   64
#define W_   64
#define HID  64
#define KCH  100      // s*s*k*k
#define SS   4        // s*s
#define KK   25       // k*k
#define HW   4096     // H*W
#define BN_EPS 1e-5f

// Scratch (static device allocations — allowed; zero-initialized at load)
__device__ float  g_h[B_ * HID * HW];       // 4 MB
__device__ float  g_kern[B_ * KCH * HW];    // 6.55 MB
__device__ float  g_sc[HID];
__device__ float  g_sh[HID];
__device__ double g_sum[HID];               // BN stats accumulators
__device__ double g_sum2[HID];              // (re-zeroed by k2_fin each call)

// ---------------------------------------------------------------------------
// cp.async helpers (4-byte, zero-fill via src-size=0 for OOB)
// ---------------------------------------------------------------------------
__device__ __forceinline__ void cp_async_f32(uint32_t smem_addr,
                                             const float* gptr, bool valid)
{
    const int sz = valid ? 4 : 0;
    asm volatile("cp.async.ca.shared.global [%0], [%1], 4, %2;\n"
                 :: "r"(smem_addr), "l"(gptr), "r"(sz));
}
#define CP_COMMIT() asm volatile("cp.async.commit_group;\n" ::: "memory")
#define CP_WAIT0()  asm volatile("cp.async.wait_group 0;\n" ::: "memory")

// ---------------------------------------------------------------------------
// Kernel 1: h[b,o,p] = sum_c w1[o,c] * x[b,c,p]  + fused BN partial stats.
// grid (16, B, 4) = 256 blocks x 256 threads (R10-proven config).
// Each block contributes per-channel sum/sum2 via double atomicAdd.
// ---------------------------------------------------------------------------
__global__ __launch_bounds__(256) void k1_gemm1(
    const float* __restrict__ x, const float* __restrict__ w1)
{
    __shared__ float4 w1s[16 * 64];   // 16 outputs x 256 c (as float4)
    __shared__ float  ws1[8][16], ws2[8][16];
    const int b  = blockIdx.y;
    const int og = blockIdx.z;
    const int tid = threadIdx.x;
    const int lane = tid & 31, wid = tid >> 5;

    const float4* w1g = (const float4*)(w1 + og * 16 * C_);
    for (int i = tid; i < 16 * 64; i += 256) w1s[i] = w1g[i];
    __syncthreads();

    const int p = blockIdx.x * 256 + tid;
    const float* xb = x + (size_t)b * C_ * HW + p;

    float acc[16];
#pragma unroll
    for (int o = 0; o < 16; o++) acc[o] = 0.f;

    for (int c = 0; c < C_; c += 4) {
        float xv0 = xb[(c + 0) * HW];
        float xv1 = xb[(c + 1) * HW];
        float xv2 = xb[(c + 2) * HW];
        float xv3 = xb[(c + 3) * HW];
#pragma unroll
        for (int o = 0; o < 16; o++) {
            float4 w = w1s[o * 64 + (c >> 2)];
            acc[o] += w.x * xv0 + w.y * xv1 + w.z * xv2 + w.w * xv3;
        }
    }

    float* hb = g_h + ((size_t)b * HID + og * 16) * HW + p;
#pragma unroll
    for (int o = 0; o < 16; o++) hb[o * HW] = acc[o];

    // BN partial stats: warp-shuffle reduce, then 16 threads atomicAdd.
#pragma unroll
    for (int o = 0; o < 16; o++) {
        float v = acc[o], v2 = v * v;
#pragma unroll
        for (int off = 16; off; off >>= 1) {
            v  += __shfl_down_sync(0xffffffffu, v,  off);
            v2 += __shfl_down_sync(0xffffffffu, v2, off);
        }
        if (lane == 0) { ws1[wid][o] = v; ws2[wid][o] = v2; }
    }
    __syncthreads();
    if (tid < 16) {
        float s1 = 0.f, s2 = 0.f;
#pragma unroll
        for (int w = 0; w < 8; w++) { s1 += ws1[w][tid]; s2 += ws2[w][tid]; }
        atomicAdd(&g_sum [og * 16 + tid], (double)s1);
        atomicAdd(&g_sum2[og * 16 + tid], (double)s2);
    }
}

// ---------------------------------------------------------------------------
// Kernel 2 (micro): finalize BN scale/shift from accumulated stats,
// then re-zero accumulators for the next graph replay.
// ---------------------------------------------------------------------------
__global__ void k2_fin(const float* __restrict__ gamma,
                       const float* __restrict__ beta)
{
    const int o = threadIdx.x;   // 64 threads
    const double invN = 1.0 / (double)(B_ * HW);
    double mean = g_sum[o] * invN;
    double var  = g_sum2[o] * invN - mean * mean;
    float scale = gamma[o] * rsqrtf((float)var + BN_EPS);
    g_sc[o] = scale;
    g_sh[o] = beta[o] - (float)mean * scale;
    g_sum[o]  = 0.0;
    g_sum2[o] = 0.0;
}

// ---------------------------------------------------------------------------
// Kernel 3 (R10-proven): BN apply + ReLU + GEMM2 + softmax, per s-group.
// grid (16, B, SS) = 256 blocks x 256 threads.
// ---------------------------------------------------------------------------
__global__ __launch_bounds__(256) void k3_kern(
    const float* __restrict__ w2, const float* __restrict__ b2)
{
    __shared__ float4 w2s[KK * 16];   // 25 outputs x 64 c (as float4)
    __shared__ float b2s[KK], scs[HID], shs[HID];
    const int b = blockIdx.y, g = blockIdx.z, tid = threadIdx.x;

    const float4* w2g = (const float4*)(w2 + g * KK * HID);
    for (int i = tid; i < KK * 16; i += 256) w2s[i] = w2g[i];
    if (tid < KK)  b2s[tid] = b2[g * KK + tid];
    if (tid < HID) { scs[tid] = g_sc[tid]; shs[tid] = g_sh[tid]; }
    __syncthreads();

    const int p = blockIdx.x * 256 + tid;
    const float* hb = g_h + (size_t)b * HID * HW + p;

    float a[HID];
#pragma unroll
    for (int c = 0; c < HID; c++)
        a[c] = fmaxf(fmaf(hb[c * HW], scs[c], shs[c]), 0.f);

    float v[KK];
    float vmax = -1e30f;
#pragma unroll
    for (int q = 0; q < KK; q++) {
        float acc = b2s[q];
#pragma unroll
        for (int c4 = 0; c4 < 16; c4++) {
            float4 w = w2s[q * 16 + c4];
            acc += w.x * a[4 * c4] + w.y * a[4 * c4 + 1]
                 + w.z * a[4 * c4 + 2] + w.w * a[4 * c4 + 3];
        }
        v[q] = acc;
        vmax = fmaxf(vmax, acc);
    }
    float ssum = 0.f;
#pragma unroll
    for (int q = 0; q < KK; q++) { v[q] = __expf(v[q] - vmax); ssum += v[q]; }
    float inv = 1.f / ssum;

    float* kb = g_kern + ((size_t)b * KCH + g * KK) * HW + p;
#pragma unroll
    for (int q = 0; q < KK; q++) kb[q * HW] = v[q] * inv;
}

// ---------------------------------------------------------------------------
// Kernel 4 (v4, unchanged from R12): reassembly + pixel shuffle,
// cp.async double-buffered halo. 38.8us verified.
// ---------------------------------------------------------------------------
#define CSPLIT 4
#define CPB    (C_ / CSPLIT)     // 64 channels per block
#define TW4 16
#define TH4 4
#define HWID 20                  // halo width
#define HHGT 8                   // halo height
#define NQ  4                    // channel-quads per phase (16 channels)
#define HSLOTS (NQ * HHGT * HWID)  // 640 float4 slots
#define NPHASE (CPB / (NQ * 4))    // 4
#define LPT (HSLOTS / 128)         // 5 halo slots per thread

__global__ __launch_bounds__(128, 5) void k4_reassemble(
    const float* __restrict__ x, float* __restrict__ out)
{
    __shared__ float4 xs4[2][HSLOTS];   // 2 x 10 KB

    const int bz    = blockIdx.z;
    const int b     = bz >> 2;            // CSPLIT = 4
    const int cbase = (bz & 3) * CPB;
    const int tid   = threadIdx.x;
    const int lane  = tid & 31;
    const int wrow  = tid >> 5;           // tile row 0..3
    const int pxl   = lane & 15;
    const int si    = lane >> 4;          // 0 or 1
    const int px    = blockIdx.x * TW4 + pxl;
    const int py    = blockIdx.y * TH4 + wrow;
    const int p     = py * W_ + px;

    const float* xb = x + (size_t)b * C_ * HW;
    const int h0 = blockIdx.y * TH4 - 2;
    const int w0 = blockIdx.x * TW4 - 2;

    // Per-thread halo-load slots (fixed across phases)
    int  goff[LPT];
    bool gval[LPT];
#pragma unroll
    for (int j = 0; j < LPT; j++) {
        const int i   = tid + j * 128;
        const int q   = i / (HHGT * HWID);
        const int rem = i - q * (HHGT * HWID);
        const int r   = rem / HWID;
        const int cc  = rem - r * HWID;
        const int gh = h0 + r, gw = w0 + cc;
        gval[j] = ((unsigned)gh < (unsigned)H_) && ((unsigned)gw < (unsigned)W_);
        goff[j] = (q * 4) * HW + (gval[j] ? (gh * W_ + gw) : 0);
    }

    // Issue phase-0 halo via cp.async (overlaps with the kr LDGs below)
    {
        const float* base = xb + (size_t)cbase * HW;
#pragma unroll
        for (int j = 0; j < LPT; j++) {
            const uint32_t sdst =
                (uint32_t)__cvta_generic_to_shared(&xs4[0][tid + j * 128]);
            const float* gp = base + goff[j];
#pragma unroll
            for (int k = 0; k < 4; k++)
                cp_async_f32(sdst + 4 * k, gp + k * HW, gval[j]);
        }
        CP_COMMIT();
    }

    // 50 softmax weights: groups si*2+0 and si*2+1
    float kr[50];
    {
        const float* kb = g_kern + ((size_t)b * KCH + si * 50) * HW + p;
#pragma unroll
        for (int j = 0; j < 50; j++) kr[j] = kb[j * HW];
    }

    float* ob = out + (size_t)b * C_ * (4 * HW)
              + (size_t)(2 * py + si) * (2 * W_) + 2 * px;

    CP_WAIT0();
    __syncthreads();

#pragma unroll 1
    for (int phase = 0; phase < NPHASE; phase++) {
        const int cph = cbase + phase * (NQ * 4);
        const int buf = phase & 1;
        const bool has_next = (phase + 1 < NPHASE);

        // Issue next phase's halo into the other buffer (async, no regs held)
        if (has_next) {
            const float* base = xb + (size_t)(cph + NQ * 4) * HW;
#pragma unroll
            for (int j = 0; j < LPT; j++) {
                const uint32_t sdst =
                    (uint32_t)__cvta_generic_to_shared(&xs4[buf ^ 1][tid + j * 128]);
                const float* gp = base + goff[j];
#pragma unroll
                for (int k = 0; k < 4; k++)
                    cp_async_f32(sdst + 4 * k, gp + k * HW, gval[j]);
            }
            CP_COMMIT();
        }

        // Compute from current buffer
#pragma unroll 1
        for (int q = 0; q < NQ; q++) {
            const float4* t = xs4[buf] + (q * HHGT + wrow) * HWID + pxl;
            float ax0 = 0.f, ay0 = 0.f, az0 = 0.f, aw0 = 0.f;   // sj = 0
            float ax1 = 0.f, ay1 = 0.f, az1 = 0.f, aw1 = 0.f;   // sj = 1
#pragma unroll
            for (int di = 0; di < 5; di++) {
#pragma unroll
                for (int dj = 0; dj < 5; dj++) {
                    const float4 xv = t[di * HWID + dj];
                    const float wA = kr[di * 5 + dj];
                    const float wB = kr[25 + di * 5 + dj];
                    ax0 = fmaf(wA, xv.x, ax0);  ax1 = fmaf(wB, xv.x, ax1);
                    ay0 = fmaf(wA, xv.y, ay0);  ay1 = fmaf(wB, xv.y, ay1);
                    az0 = fmaf(wA, xv.z, az0);  az1 = fmaf(wB, xv.z, az1);
                    aw0 = fmaf(wA, xv.w, aw0);  aw1 = fmaf(wB, xv.w, aw1);
                }
            }
            float* oc = ob + (size_t)(cph + q * 4) * (4 * HW);
            *(float2*)oc = make_float2(ax0, ax1);  oc += 4 * HW;
            *(float2*)oc = make_float2(ay0, ay1);  oc += 4 * HW;
            *(float2*)oc = make_float2(az0, az1);  oc += 4 * HW;
            *(float2*)oc = make_float2(aw0, aw1);
        }

        if (has_next) {
            CP_WAIT0();
            __syncthreads();
        }
    }
}

// ---------------------------------------------------------------------------
extern "C" void kernel_launch(void* const* d_in, const int* in_sizes, int n_in,
                              void* d_out, int out_size)
{
    const float* x     = (const float*)d_in[0];   // [4,256,64,64]
    const float* w1    = (const float*)d_in[1];   // [64,256]
    const float* gamma = (const float*)d_in[2];   // [64]
    const float* beta  = (const float*)d_in[3];   // [64]
    const float* w2    = (const float*)d_in[4];   // [100,64]
    const float* b2    = (const float*)d_in[5];   // [100]
    float* out = (float*)d_out;                   // [4,256,128,128]

    k1_gemm1<<<dim3(16, B_, 4), 256>>>(x, w1);
    k2_fin<<<1, HID>>>(gamma, beta);
    k3_kern<<<dim3(16, B_, SS), 256>>>(w2, b2);
    k4_reassemble<<<dim3(W_ / TW4, H_ / TH4, B_ * CSPLIT), 128>>>(x, out);
}